// round 17
// baseline (speedup 1.0000x reference)
#include <cuda_runtime.h>

#define BB 16
#define NN 4096
#define CC 1024
#define HH 16
#define DD 64

#define XPARTS 9                  // 9*16 = 144 blocks = ONE wave on 148 SMs
#define CSPLIT 16
#define FT 16                     // rows per tile (64 KB)
#define NTILES_TOTAL (NN/FT)      // 256 tiles per batch
#define RING 2                    // xs ring depth

typedef unsigned long long u64;

__device__ __forceinline__ u64 pack2(float lo, float hi) {
    u64 r; asm("mov.b64 %0, {%1, %2};" : "=l"(r) : "f"(lo), "f"(hi)); return r;
}
__device__ __forceinline__ void unpack2(u64 v, float& lo, float& hi) {
    asm("mov.b64 {%0, %1}, %2;" : "=f"(lo), "=f"(hi) : "l"(v));
}
__device__ __forceinline__ void ffma2(u64& d, u64 a, u64 b) {
    asm("fma.rn.f32x2 %0, %1, %2, %0;" : "+l"(d) : "l"(a), "l"(b));
}

// mbarrier + bulk-copy helpers
__device__ __forceinline__ void mbar_init(unsigned addr, unsigned cnt) {
    asm volatile("mbarrier.init.shared.b64 [%0], %1;" :: "r"(addr), "r"(cnt) : "memory");
}
__device__ __forceinline__ void mbar_expect_tx(unsigned addr, unsigned bytes) {
    asm volatile("mbarrier.arrive.expect_tx.shared.b64 _, [%0], %1;"
                 :: "r"(addr), "r"(bytes) : "memory");
}
__device__ __forceinline__ void mbar_arrive(unsigned addr) {
    asm volatile("mbarrier.arrive.shared.b64 _, [%0];" :: "r"(addr) : "memory");
}
__device__ __forceinline__ void bulk_ld(unsigned dst_smem, const void* src,
                                        unsigned bytes, unsigned mbar_addr) {
    asm volatile("cp.async.bulk.shared::cluster.global.mbarrier::complete_tx::bytes "
                 "[%0], [%1], %2, [%3];"
                 :: "r"(dst_smem), "l"(src), "r"(bytes), "r"(mbar_addr) : "memory");
}
__device__ __forceinline__ void mbar_wait(unsigned addr, int ph) {
    asm volatile(
        "{\n\t.reg .pred P;\n\t"
        "WL_%=:\n\t"
        "mbarrier.try_wait.parity.acquire.cta.shared::cta.b64 P, [%0], %1, 0x989680;\n\t"
        "@P bra.uni WD_%=;\n\t"
        "bra.uni WL_%=;\n\t"
        "WD_%=:\n\t}"
        :: "r"(addr), "r"(ph) : "memory");
}
#define BAR_SYNC(id, cnt)   asm volatile("bar.sync %0, %1;"   :: "r"(id), "r"(cnt) : "memory")
#define BAR_ARRIVE(id, cnt) asm volatile("bar.arrive %0, %1;" :: "r"(id), "r"(cnt) : "memory")

// Persistent scratch (allocation-free rule: __device__ globals)
__device__ float g_watt[BB*HH*CC];          // folded attn weights [b][h][c]
__device__ float g_xap[XPARTS*BB*HH*CC];    // xa partials [p][b][h][c]
__device__ float g_dpart[XPARTS*BB*HH];     // denom partials [p][b][h]
__device__ float g_xa[BB*HH*CC];            // attn-weighted x [b][h][c]
__device__ float g_clsp[CSPLIT*BB*CC];      // cls partials [cp][b][j]
__device__ float g_cls[BB*CC];              // cls embedding [b][h*64+d]

// ---------------------------------------------------------------------------
// No-op kernel: launch-slot padding so ncu's capture index lands on k_fused.
// ---------------------------------------------------------------------------
__global__ void k_nop() {}

// ---------------------------------------------------------------------------
// Kernel 1: per (b,h): q = scale * x[b,0,:] @ Wq[:,h,:]; then
// w_att[b,h,c] = sum_d Wkv_k[c,h,d] * q[d].
// ---------------------------------------------------------------------------
__global__ void k_watt(const float* __restrict__ x,
                       const float* __restrict__ Wq,
                       const float* __restrict__ Wkv) {
    int b = blockIdx.x >> 4;
    int h = blockIdx.x & 15;
    int t = threadIdx.x;   // 256
    __shared__ float xs[CC];
    __shared__ float qpart[256];
    __shared__ float qs[DD];

    const float* xrow = x + (size_t)b * NN * CC;
    for (int c = t; c < CC; c += 256) xs[c] = xrow[c];
    __syncthreads();

    {
        int d = t >> 2, part = t & 3;
        const float* wq = Wq + h * DD + d;
        float acc = 0.f;
        int c0 = part * 256;
        #pragma unroll 8
        for (int c = c0; c < c0 + 256; ++c)
            acc += xs[c] * wq[(size_t)c * (HH * DD)];
        qpart[t] = acc;
    }
    __syncthreads();
    if (t < DD) {
        float q = qpart[t*4] + qpart[t*4+1] + qpart[t*4+2] + qpart[t*4+3];
        qs[t] = q * 0.125f;
    }
    __syncthreads();

    for (int c = t; c < CC; c += 256) {
        const float4* wk = (const float4*)(Wkv + (size_t)c * (2*HH*DD) + h * DD);
        float s = 0.f;
        #pragma unroll
        for (int j4 = 0; j4 < DD/4; ++j4) {
            float4 w = wk[j4];
            s += w.x * qs[j4*4+0] + w.y * qs[j4*4+1]
               + w.z * qs[j4*4+2] + w.w * qs[j4*4+3];
        }
        g_watt[((size_t)b*HH + h)*CC + c] = s;
    }
}

// ---------------------------------------------------------------------------
// Kernel 2: FUSED warp-specialized pipeline, 1024 threads (8 warps/SMSP).
//   Warps 0-15  (t<512):  logits -> s_red[slot]   (w2: 32 regs)
//   Warps 16-31 (t>=512): exp+denom, then xa      (acc: 32 regs)
// __launch_bounds__(1024,1) caps regs at 64/thread so the whole CTA fits the
// register file with double the warp supply of the 512-thread version.
// Named barriers: 1+s = SRED_RDY(s), 3+s = SLOT_FREE(s) (s=0..1),
//                 5 = xa-internal (ps complete).
// ---------------------------------------------------------------------------
__global__ void __launch_bounds__(1024, 1) k_fused(const float* __restrict__ x) {
    int part = blockIdx.x;     // 0..8
    int b    = blockIdx.y;
    int t    = threadIdx.x;    // 1024
    int lane = t & 31;

    int tile0  = part * NTILES_TOTAL / XPARTS;
    int tile1  = (part + 1) * NTILES_TOTAL / XPARTS;
    int ntiles = tile1 - tile0;             // 28 or 29

    extern __shared__ __align__(128) float dyn[];
    float* xs    = dyn;                     // RING*FT*CC   (128 KB)
    float* s_red = dyn + RING*FT*CC;        // RING*FT*16*16 (32 KB)
    __shared__ __align__(16) float ps[RING][FT*16];   // 2 KB
    __shared__ float dred[256];
    __shared__ __align__(8) u64 mbar_full[RING];
    __shared__ __align__(8) u64 mbar_empty[RING];

    unsigned mbf[RING], mbe[RING], xsa[RING];
    #pragma unroll
    for (int s = 0; s < RING; ++s) {
        mbf[s] = (unsigned)__cvta_generic_to_shared(&mbar_full[s]);
        mbe[s] = (unsigned)__cvta_generic_to_shared(&mbar_empty[s]);
        xsa[s] = (unsigned)__cvta_generic_to_shared(&xs[s*FT*CC]);
    }

    if (t == 0) {
        #pragma unroll
        for (int s = 0; s < RING; ++s) {
            mbar_init(mbf[s], 1);
            mbar_init(mbe[s], 32);   // 32 consumer warps (lane 0 each)
        }
    }
    __syncthreads();

    const float* xb = x + ((size_t)b*NN + (size_t)tile0*FT)*CC;
    const unsigned TILE_BYTES = FT*CC*4;   // 65536

    #define ISSUE(bt) do {                                             \
        int _s = (bt) & (RING-1);                                      \
        mbar_expect_tx(mbf[_s], TILE_BYTES);                           \
        bulk_ld(xsa[_s], xb + (size_t)(bt)*FT*CC, TILE_BYTES, mbf[_s]);\
    } while (0)

    if (t == 512) {
        #pragma unroll
        for (int k = 0; k < RING; ++k) if (k < ntiles) ISSUE(k);
    }

    if (t < 512) {
        // ================= LOGITS SIDE (16 warps) =================
        int hg   = t & 3;
        int sidx = t >> 2;    // 0..127 -> 8-float c slice
        int w    = t >> 5;    // warp 0..15
        int myhead = (lane & 3) + 8*((lane >> 2) & 1) + 4*((lane >> 3) & 1);

        u64 w2[4][4];         // 4 heads x 8 c packed -> 32 regs
        #pragma unroll
        for (int g = 0; g < 4; ++g) {
            const ulonglong2* wp =
                (const ulonglong2*)(g_watt + ((size_t)b*HH + hg + 4*g)*CC + sidx*8);
            ulonglong2 v0 = wp[0], v1 = wp[1];
            w2[g][0] = v0.x; w2[g][1] = v0.y; w2[g][2] = v1.x; w2[g][3] = v1.y;
        }

        for (int bt = 0; bt < ntiles; ++bt) {
            int slot = bt & (RING-1), ph = (bt >> 1) & 1;
            if (bt >= RING) BAR_SYNC(3 + slot, 1024);  // s_red/ps slot free
            mbar_wait(mbf[slot], ph);                  // tile data ready

            const float* xt = xs + slot*FT*CC;
            float* sr = s_red + slot*FT*16*16;
            #pragma unroll
            for (int r = 0; r < FT; ++r) {
                const ulonglong2* xp = (const ulonglong2*)(xt + r*CC + sidx*8);
                ulonglong2 a0 = xp[0], a1 = xp[1];
                u64 xx0 = a0.x, xx1 = a0.y, xx2 = a1.x, xx3 = a1.y;

                u64 p2[4] = {0ull, 0ull, 0ull, 0ull};
                #pragma unroll
                for (int g = 0; g < 4; ++g) {
                    ffma2(p2[g], xx0, w2[g][0]);
                    ffma2(p2[g], xx1, w2[g][1]);
                    ffma2(p2[g], xx2, w2[g][2]);
                    ffma2(p2[g], xx3, w2[g][3]);
                }

                float v0, v1, v2, v3;
                {   float lo, hi;
                    unpack2(p2[0], lo, hi); v0 = lo + hi;
                    unpack2(p2[1], lo, hi); v1 = lo + hi;
                    unpack2(p2[2], lo, hi); v2 = lo + hi;
                    unpack2(p2[3], lo, hi); v3 = lo + hi;
                }
                // specialized butterfly: 4 shfl total
                bool b2 = (lane & 4) != 0;
                float keepA = b2 ? v2 : v0, sendA = b2 ? v0 : v2;
                float keepB = b2 ? v3 : v1, sendB = b2 ? v1 : v3;
                keepA += __shfl_xor_sync(0xffffffffu, sendA, 4);
                keepB += __shfl_xor_sync(0xffffffffu, sendB, 4);
                bool b3 = (lane & 8) != 0;
                float keep = b3 ? keepB : keepA, send = b3 ? keepA : keepB;
                keep += __shfl_xor_sync(0xffffffffu, send, 8);
                keep += __shfl_xor_sync(0xffffffffu, keep, 16);
                if (lane < 16) sr[(r*16 + w)*16 + myhead] = keep;
            }
            BAR_ARRIVE(1 + slot, 1024);                // s_red ready for xa
            if (lane == 0) mbar_arrive(mbe[slot]);     // done reading xs[slot]
        }
    } else {
        // ================= XA SIDE (16 warps) =================
        int tt = t - 512;       // 0..511 -> 2 contiguous c
        u64 acc[8][2];          // 16 heads x 2 c packed -> 32 regs
        #pragma unroll
        for (int hp = 0; hp < 8; ++hp) { acc[hp][0] = 0ull; acc[hp][1] = 0ull; }
        float dsum = 0.f;

        for (int bt = 0; bt < ntiles; ++bt) {
            int slot = bt & (RING-1), ph = (bt >> 1) & 1;
            BAR_SYNC(1 + slot, 1024);                  // s_red ready (=> xs ready)

            // exp + denom: threads tt<256 handle one (row, head)
            const float* sr = s_red + slot*FT*16*16;
            if (tt < 256) {
                int rr = tt >> 4, hh = tt & 15;
                float s = 0.f;
                #pragma unroll
                for (int ww = 0; ww < 16; ++ww) s += sr[(rr*16 + ww)*16 + hh];
                float e = __expf(s);
                ps[slot][rr*16 + hh] = e;
                dsum += e;
            }
            BAR_SYNC(5, 512);                          // ps complete (xa-internal)

            const float* xt = xs + slot*FT*CC;
            #pragma unroll
            for (int r = 0; r < FT; ++r) {
                float2 xv = *(const float2*)(xt + r*CC + tt*2);
                const ulonglong2* pr = (const ulonglong2*)(ps[slot] + r*16);
                ulonglong2 q0 = pr[0], q1 = pr[1], q2 = pr[2], q3 = pr[3];
                u64 pp[8] = {q0.x, q0.y, q1.x, q1.y, q2.x, q2.y, q3.x, q3.y};

                u64 xx0 = pack2(xv.x, xv.x);
                u64 xx1 = pack2(xv.y, xv.y);
                #pragma unroll
                for (int hp = 0; hp < 8; ++hp) {
                    ffma2(acc[hp][0], pp[hp], xx0);
                    ffma2(acc[hp][1], pp[hp], xx1);
                }
            }
            BAR_ARRIVE(3 + slot, 1024);                // s_red/ps slot free
            if (lane == 0) mbar_arrive(mbe[slot]);     // done reading xs[slot]
            if (t == 512 && bt + RING < ntiles) {
                mbar_wait(mbe[slot], ph);              // all 32 warps released slot
                ISSUE(bt + RING);
            }
        }
        if (tt < 256) dred[tt] = dsum;

        // epilogue: plain vector stores to private partial tile
        int c0 = tt * 2;
        float* basep = g_xap + (((size_t)part*BB + b)*HH)*CC;
        #pragma unroll
        for (int hp = 0; hp < 8; ++hp) {
            float a0lo, a0hi, a1lo, a1hi;
            unpack2(acc[hp][0], a0lo, a0hi);
            unpack2(acc[hp][1], a1lo, a1hi);
            *(float2*)(basep + (size_t)(2*hp    )*CC + c0) = make_float2(a0lo, a1lo);
            *(float2*)(basep + (size_t)(2*hp + 1)*CC + c0) = make_float2(a0hi, a1hi);
        }
    }
    #undef ISSUE

    __syncthreads();
    if (t < 16) {
        float d = 0.f;
        #pragma unroll
        for (int k = 0; k < 16; ++k) d += dred[t + 16*k];
        g_dpart[((size_t)part*BB + b)*HH + t] = d;
    }
}

// ---------------------------------------------------------------------------
// Kernel 3: fold the 9 partial tiles into g_xa (pure streaming).
// ---------------------------------------------------------------------------
__global__ void k_xared() {
    int bh = blockIdx.x;   // 0..255
    int t  = threadIdx.x;  // 256
    int c  = t * 4;
    float4 s = make_float4(0.f, 0.f, 0.f, 0.f);
    #pragma unroll
    for (int p = 0; p < XPARTS; ++p) {
        float4 v = *(const float4*)(g_xap + ((size_t)p*BB*HH + bh)*CC + c);
        s.x += v.x; s.y += v.y; s.z += v.z; s.w += v.w;
    }
    *(float4*)(g_xa + (size_t)bh*CC + c) = s;
}

// ---------------------------------------------------------------------------
// Kernel 4a: cls partials, coalesced Wkv reads.
// ---------------------------------------------------------------------------
__global__ void __launch_bounds__(256) k_clsp(const float* __restrict__ Wkv) {
    int cp = blockIdx.x;      // 0..15 -> c in [cp*64, cp*64+64)
    int b  = blockIdx.y;
    int t  = threadIdx.x;     // 256
    int c0 = cp * 64;
    int j  = t * 4;
    int h  = t >> 4;

    __shared__ __align__(16) float xas[HH*64];
    {
        int i = t * 4;
        int hh = i >> 6, cc = i & 63;
        *(float4*)(xas + i) =
            *(const float4*)(g_xa + ((size_t)b*HH + hh)*CC + c0 + cc);
    }
    __syncthreads();

    const float* wbase = Wkv + (size_t)c0 * (2*HH*DD) + (HH*DD) + j;
    float4 acc = make_float4(0.f, 0.f, 0.f, 0.f);

    #pragma unroll 4
    for (int cc = 0; cc < 64; ++cc) {
        float xv = xas[h*64 + cc];
        float4 wv = *(const float4*)(wbase + (size_t)cc * (2*HH*DD));
        acc.x += xv * wv.x; acc.y += xv * wv.y;
        acc.z += xv * wv.z; acc.w += xv * wv.w;
    }

    *(float4*)(g_clsp + ((size_t)cp*BB + b)*CC + j) = acc;
}

// ---------------------------------------------------------------------------
// Kernel 4b: fold cls partials, apply 1/denom, seed out with bproj.
// ---------------------------------------------------------------------------
__global__ void k_clsred(const float* __restrict__ bproj,
                         float* __restrict__ out) {
    int b = blockIdx.x;       // 0..15
    int t = threadIdx.x;      // 256
    int j = t * 4;
    int h = t >> 4;

    float den = 0.f;
    #pragma unroll
    for (int p = 0; p < XPARTS; ++p)
        den += g_dpart[((size_t)p*BB + b)*HH + h];
    float inv = 1.0f / den;

    float4 s = make_float4(0.f, 0.f, 0.f, 0.f);
    #pragma unroll
    for (int p = 0; p < CSPLIT; ++p) {
        float4 v = *(const float4*)(g_clsp + ((size_t)p*BB + b)*CC + j);
        s.x += v.x; s.y += v.y; s.z += v.z; s.w += v.w;
    }
    s.x *= inv; s.y *= inv; s.z *= inv; s.w *= inv;
    *(float4*)(g_cls + (size_t)b*CC + j) = s;
    *(float4*)(out + (size_t)b*CC + j) = *(const float4*)(bproj + j);
}

// ---------------------------------------------------------------------------
// Kernel 5: out[b,j] += sum_i cls[b,i] * Wproj[i,j]
// ---------------------------------------------------------------------------
__global__ void k_proj(const float* __restrict__ Wproj,
                       float* __restrict__ out) {
    int jc = blockIdx.x;   // 0..3
    int ic = blockIdx.y;   // 0..3
    int b  = blockIdx.z;   // 0..15
    int tt = threadIdx.x;  // 256
    int j  = jc*256 + tt;

    __shared__ float cs[256];
    cs[tt] = g_cls[(size_t)b*CC + ic*256 + tt];
    __syncthreads();

    const float* wp = Wproj + (size_t)(ic*256) * CC + j;
    float acc = 0.f;
    #pragma unroll 8
    for (int i = 0; i < 256; ++i)
        acc += cs[i] * wp[(size_t)i * CC];
    atomicAdd(&out[(size_t)b*CC + j], acc);
}

// ---------------------------------------------------------------------------
extern "C" void kernel_launch(void* const* d_in, const int* in_sizes, int n_in,
                              void* d_out, int out_size) {
    const float* x     = (const float*)d_in[0];
    const float* Wq    = (const float*)d_in[1];
    const float* Wkv   = (const float*)d_in[2];
    const float* Wproj = (const float*)d_in[3];
    const float* bproj = (const float*)d_in[4];
    float* out = (float*)d_out;

    const int DYN = RING*FT*CC*4 + RING*FT*16*16*4;   // 128 KB + 32 KB

    static bool attr_set = false;
    if (!attr_set) {
        cudaFuncSetAttribute(k_fused, cudaFuncAttributeMaxDynamicSharedMemorySize,
                             DYN);
        attr_set = true;
    }

    k_watt   <<<BB*HH, 256>>>(x, Wq, Wkv);
    k_nop    <<<1, 32>>>();   // launch-slot padding: keep k_fused at the
    k_nop    <<<1, 32>>>();   // ncu capture index (4th launch)
    k_fused  <<<dim3(XPARTS, BB), 1024, DYN>>>(x);
    k_xared  <<<BB*HH, 256>>>();
    k_clsp   <<<dim3(CSPLIT, BB), 256>>>(Wkv);
    k_clsred <<<BB, 256>>>(bproj, out);
    k_proj   <<<dim3(4, 4, BB), 256>>>(Wproj, out);
}